// round 12
// baseline (speedup 1.0000x reference)
#include <cuda_runtime.h>
#include <cstdint>
#include <math.h>
#include <math_constants.h>

typedef unsigned int u32;

#define E_  64
#define A_  8
#define L_  2048
#define D_  128
#define H_  8
#define DK_ 16

#define NB_     (E_ * A_)      // 512 (e,a) pairs
#define NCHUNK  4
#define CHUNK   (L_ / NCHUNK)  // 512 rows per chunk

#define NSTAGE  4
#define SROWS   24             // rows per stage (3 per warp)
#define STG_F4  (SROWS * 32)   // float4 per stage

// ---------------------------------------------------------------------------
// Device scratch (no cudaMalloc allowed)
// ---------------------------------------------------------------------------
__device__ float  g_U[NB_ * H_ * D_];            // folded query vectors (2 MB)
__device__ float  g_W3t[H_ * D_ * D_];           // [h][o][d] folded K-side (512 KB)
__device__ float  g_Wv_eff[H_ * (D_ + 1) * DK_]; // Wv_proj @ Wv[h]
__device__ float  g_P[NB_ * NCHUNK * H_ * D_];   // unnormalized partial acc
__device__ float2 g_S[NB_ * NCHUNK * H_];        // (m, Z) per partial

// ---------------------------------------------------------------------------
__device__ __forceinline__ void cp_async16(u32 dst, const void* src, int sz) {
    asm volatile("cp.async.cg.shared.global [%0], [%1], 16, %2;\n"
                 :: "r"(dst), "l"(src), "r"(sz) : "memory");
}
#define CP_COMMIT() asm volatile("cp.async.commit_group;\n" ::: "memory")
#define CP_WAIT3()  asm volatile("cp.async.wait_group 3;\n" ::: "memory")
#define CP_WAIT0()  asm volatile("cp.async.wait_group 0;\n" ::: "memory")

// ---------------------------------------------------------------------------
// fold_kernel: grid 24.
//  blocks [0,16):  (h = bid>>1, pass p = bid&1) ->
//      W2[j][o] = sum_k Wk[h][j,k]*Wq[h][o,k]        (o in 64p..64p+63, smem)
//      g_W3t[h][o][d] = 0.25 * sum_j Wk_proj[d,j]*W2[j][o]
//  blocks [16,24): h = bid-16 ->
//      g_Wv_eff[h][d][k] = sum_j Wv_proj[d,j]*Wv[h][j,k]   (d in 0..128)
// ---------------------------------------------------------------------------
__global__ void __launch_bounds__(256)
fold_kernel(const float* __restrict__ Wq_proj,  // unused here (kept for sig sym)
            const float* __restrict__ Wk_proj,
            const float* __restrict__ Wv_proj,
            const float* __restrict__ Wq,
            const float* __restrict__ Wk,
            const float* __restrict__ Wv) {
    int tid = threadIdx.x;
    int bid = blockIdx.x;
    (void)Wq_proj;

    if (bid < 16) {
        int h = bid >> 1;
        int p = bid & 1;
        __shared__ float w2_s[128 * 64];          // 32 KB

        const float* wqh = Wq + h * (D_ * DK_);
        const float* wkh = Wk + h * (D_ * DK_);

        // W2 chunk: 8192 outputs (j, ol)
#pragma unroll 4
        for (int t = 0; t < 32; t++) {
            int idx = t * 256 + tid;
            int j  = idx >> 6;
            int ol = idx & 63;
            const float* wkr = wkh + j * DK_;
            const float* wqr = wqh + (64 * p + ol) * DK_;
            float s = 0.f;
#pragma unroll
            for (int k = 0; k < DK_; k++) s = fmaf(wkr[k], wqr[k], s);
            w2_s[j * 64 + ol] = s;
        }
        __syncthreads();

        // W3t: 8192 outputs (ol, d)
        for (int t = 0; t < 32; t++) {
            int idx = t * 256 + tid;
            int ol = idx >> 7;
            int d  = idx & 127;
            const float* wpr = Wk_proj + d * D_;
            const float* w2c = w2_s + ol;
            float s = 0.f;
#pragma unroll 4
            for (int j = 0; j < D_; j++) s = fmaf(wpr[j], w2c[j * 64], s);
            g_W3t[h * (D_ * D_) + (64 * p + ol) * D_ + d] = 0.25f * s;
        }
        return;
    }

    // ---- Wv_eff ----
    {
        int h = bid - 16;
        const float* wvh = Wv + h * (D_ * DK_);
        for (int idx = tid; idx < (D_ + 1) * DK_; idx += 256) {
            int d = idx >> 4, k = idx & 15;
            const float* wp = Wv_proj + d * D_;
            const float* wv = wvh + k;
            float s = 0.f;
#pragma unroll 4
            for (int j = 0; j < D_; j++) s = fmaf(wp[j], wv[j * DK_], s);
            g_Wv_eff[h * (D_ + 1) * DK_ + idx] = s;
        }
    }
}

// ---------------------------------------------------------------------------
// u_kernel: grid 64 (one CTA per e). Computes q for all 8 agents (context part
// shared), then u[e,a,h,d] = sum_o W3t[h][o][d] * q[a][o] with 8-agent reuse.
// ---------------------------------------------------------------------------
__global__ void __launch_bounds__(256)
u_kernel(const float* __restrict__ gc,  const float* __restrict__ de,
         const float* __restrict__ tb,  const float* __restrict__ load,
         const float* __restrict__ Wq_proj) {
    int e   = blockIdx.x;
    int tid = threadIdx.x;

    __shared__ float x_s[384];
    __shared__ float prt[256];
    __shared__ float q_s[A_ * D_];     // [a][o]

    // load context vector
    for (int i = tid; i < 384; i += 256) {
        float v;
        if (i < 128)      v = gc[e * D_ + i];
        else if (i < 256) v = de[e * D_ + (i - 128)];
        else              v = tb[e * D_ + (i - 256)];
        x_s[i] = v;
    }
    __syncthreads();

    // q_ctx[o] = sum_{i<384} x[i] * Wq_proj[i,o]   (split over two halves)
    {
        int o = tid & 127, half = tid >> 7;
        int i0 = half * 192, i1 = i0 + 192;
        float s = 0.f;
#pragma unroll 4
        for (int i = i0; i < i1; i++)
            s = fmaf(x_s[i], Wq_proj[i * D_ + o], s);
        prt[tid] = s;
    }
    __syncthreads();

    // per-agent q: q[a][o] = q_ctx[o] + load[e,a]*W[384,o] + a*W[385,o]
    if (tid < D_) {
        int o = tid;
        float qc = prt[o] + prt[o + 128];
        float wl = Wq_proj[384 * D_ + o];
        float wa = Wq_proj[385 * D_ + o];
#pragma unroll
        for (int a = 0; a < A_; a++) {
            float la = load[e * A_ + a];
            q_s[a * D_ + o] = fmaf(la, wl, fmaf((float)a, wa, qc));
        }
    }
    __syncthreads();

    // u[a][h][d] = sum_o W3t[h][o][d] * q[a][o]
#pragma unroll
    for (int t = 0; t < 4; t++) {
        int idx = t * 256 + tid;
        int h = idx >> 7, d = idx & 127;
        float acc[A_];
#pragma unroll
        for (int a = 0; a < A_; a++) acc[a] = 0.f;
        const float* w3 = g_W3t + h * (D_ * D_) + d;
#pragma unroll 2
        for (int o = 0; o < D_; o++) {
            float wv = w3[o * D_];
#pragma unroll
            for (int a = 0; a < A_; a++)
                acc[a] = fmaf(wv, q_s[a * D_ + o], acc[a]);
        }
#pragma unroll
        for (int a = 0; a < A_; a++)
            g_U[(((size_t)e * A_ + a) * H_ + h) * D_ + d] = acc[a];
    }
}

// ---------------------------------------------------------------------------
// fold8: per-lane partials p[0..7] (4 dims each) -> full 128-dot for head
// (lane & 7), replicated on all 4 lane-groups.
// ---------------------------------------------------------------------------
__device__ __forceinline__ float fold8(const float p[8], int lane) {
    const unsigned FULL = 0xffffffffu;
    int b0 = lane & 1, b1 = (lane >> 1) & 1, b2 = (lane >> 2) & 1;
    float q[4];
#pragma unroll
    for (int i = 0; i < 4; i++) {
        float t = b0 ? p[2 * i] : p[2 * i + 1];
        float r = __shfl_xor_sync(FULL, t, 1);
        q[i] = (b0 ? p[2 * i + 1] : p[2 * i]) + r;
    }
    float q2[2];
#pragma unroll
    for (int j = 0; j < 2; j++) {
        float t = b1 ? q[2 * j] : q[2 * j + 1];
        float r = __shfl_xor_sync(FULL, t, 2);
        q2[j] = (b1 ? q[2 * j + 1] : q[2 * j]) + r;
    }
    float t = b2 ? q2[0] : q2[1];
    float r = __shfl_xor_sync(FULL, t, 4);
    float s = (b2 ? q2[1] : q2[0]) + r;
    s += __shfl_xor_sync(FULL, s, 8);
    s += __shfl_xor_sync(FULL, s, 16);
    return s;
}

// ---------------------------------------------------------------------------
// attn kernel (R8 verbatim): 2048 CTAs; CTA = (b, chunk). Thread-private
// cp.async pipeline, no barriers in mainloop. Warp w owns rows 3w..3w+2/stage.
// ---------------------------------------------------------------------------
__global__ void __launch_bounds__(256, 2)
attn_kernel(const float* __restrict__ emb, const int* __restrict__ lens) {
    const unsigned FULL = 0xffffffffu;
    int b    = blockIdx.x >> 2;
    int c    = blockIdx.x & 3;
    int tid  = threadIdx.x;
    int w    = tid >> 5;
    int lane = tid & 31;

    __shared__ __align__(16) char smraw[NSTAGE * STG_F4 * 16];   // 49152 B
    float4* stage = (float4*)smraw;

    int len  = lens[b];
    len = max(1, min(L_, len));
    int c0   = c * CHUNK;
    int cend = min(len, c0 + CHUNK);
    int nrows = max(0, cend - c0);
    int total = (nrows + SROWS - 1) / SROWS;

    const float4* src = (const float4*)(emb + (size_t)b * L_ * D_);

    float4 u[H_];
    {
        const float* ub = g_U + (size_t)b * H_ * D_ + 4 * lane;
#pragma unroll
        for (int h = 0; h < H_; h++) u[h] = *(const float4*)(ub + h * D_);
    }

    u32 smbase = (u32)__cvta_generic_to_shared(smraw);
    u32 my_off[3];
#pragma unroll
    for (int i = 0; i < 3; i++)
        my_off[i] = (u32)(((3 * w + i) * 32 + lane) * 16);

#pragma unroll
    for (int s = 0; s < NSTAGE; s++) {
        if (s < total) {
            int rbase = c0 + s * SROWS + 3 * w;
#pragma unroll
            for (int i = 0; i < 3; i++) {
                int gr = rbase + i;
                int ok = gr < cend;
                const void* sp = src + ((size_t)(ok ? gr : c0) * 32 + lane);
                cp_async16(smbase + (u32)(s * STG_F4 * 16) + my_off[i], sp, ok ? 16 : 0);
            }
        }
        CP_COMMIT();
    }

    float4 acc[H_];
#pragma unroll
    for (int h = 0; h < H_; h++) acc[h] = make_float4(0.f, 0.f, 0.f, 0.f);
    float m = -CUDART_INF_F, Z = 0.f;
    int g = lane >> 3;

    for (int s = 0; s < total; s++) {
        CP_WAIT3();
        int buf = s & 3;
        const float4* st = stage + buf * STG_F4;
        int lr = 3 * w;
        float4 e0 = st[(lr + 0) * 32 + lane];
        float4 e1 = st[(lr + 1) * 32 + lane];
        float4 e2 = st[(lr + 2) * 32 + lane];

        float s0, s1, s2;
        {
            float pa[8];
#pragma unroll
            for (int h = 0; h < H_; h++) {
                float t = e0.x * u[h].x;
                t = fmaf(e0.y, u[h].y, t);
                t = fmaf(e0.z, u[h].z, t);
                pa[h] = fmaf(e0.w, u[h].w, t);
            }
            s0 = fold8(pa, lane);
#pragma unroll
            for (int h = 0; h < H_; h++) {
                float t = e1.x * u[h].x;
                t = fmaf(e1.y, u[h].y, t);
                t = fmaf(e1.z, u[h].z, t);
                pa[h] = fmaf(e1.w, u[h].w, t);
            }
            s1 = fold8(pa, lane);
#pragma unroll
            for (int h = 0; h < H_; h++) {
                float t = e2.x * u[h].x;
                t = fmaf(e2.y, u[h].y, t);
                t = fmaf(e2.z, u[h].z, t);
                pa[h] = fmaf(e2.w, u[h].w, t);
            }
            s2 = fold8(pa, lane);
        }

        {
            int sn = s + NSTAGE;
            if (sn < total) {
                int rbase = c0 + sn * SROWS + 3 * w;
#pragma unroll
                for (int i = 0; i < 3; i++) {
                    int gr = rbase + i;
                    int ok = gr < cend;
                    const void* sp = src + ((size_t)(ok ? gr : c0) * 32 + lane);
                    cp_async16(smbase + (u32)(buf * STG_F4 * 16) + my_off[i], sp, ok ? 16 : 0);
                }
            }
            CP_COMMIT();
        }

        int rbase = c0 + s * SROWS + 3 * w;
        if (rbase + 0 >= cend) s0 = -CUDART_INF_F;
        if (rbase + 1 >= cend) s1 = -CUDART_INF_F;
        if (rbase + 2 >= cend) s2 = -CUDART_INF_F;

        float bm = fmaxf(fmaxf(s0, s1), s2);
        if (__any_sync(FULL, bm > m)) {
            float mn = fmaxf(m, bm);
            float cs = __expf(m - mn);
            m = mn;
            Z *= cs;
#pragma unroll
            for (int h = 0; h < H_; h++) {
                float ch = __shfl_sync(FULL, cs, h);
                acc[h].x *= ch; acc[h].y *= ch; acc[h].z *= ch; acc[h].w *= ch;
            }
        }

        float sg = (g == 0) ? s0 : ((g == 1) ? s1 : s2);
        float pg = (g < 3 && sg > -CUDART_INF_F) ? __expf(sg - m) : 0.f;

        float zs = pg + __shfl_xor_sync(FULL, pg, 8);
        zs += __shfl_xor_sync(FULL, zs, 16);
        Z += zs;

#pragma unroll
        for (int h = 0; h < H_; h++) {
            float p0 = __shfl_sync(FULL, pg, 0 * 8 + h);
            acc[h].x = fmaf(p0, e0.x, acc[h].x);
            acc[h].y = fmaf(p0, e0.y, acc[h].y);
            acc[h].z = fmaf(p0, e0.z, acc[h].z);
            acc[h].w = fmaf(p0, e0.w, acc[h].w);
        }
#pragma unroll
        for (int h = 0; h < H_; h++) {
            float p1 = __shfl_sync(FULL, pg, 1 * 8 + h);
            acc[h].x = fmaf(p1, e1.x, acc[h].x);
            acc[h].y = fmaf(p1, e1.y, acc[h].y);
            acc[h].z = fmaf(p1, e1.z, acc[h].z);
            acc[h].w = fmaf(p1, e1.w, acc[h].w);
        }
#pragma unroll
        for (int h = 0; h < H_; h++) {
            float p2 = __shfl_sync(FULL, pg, 2 * 8 + h);
            acc[h].x = fmaf(p2, e2.x, acc[h].x);
            acc[h].y = fmaf(p2, e2.y, acc[h].y);
            acc[h].z = fmaf(p2, e2.z, acc[h].z);
            acc[h].w = fmaf(p2, e2.w, acc[h].w);
        }
    }

    CP_WAIT0();
    __syncthreads();

    float* sm_m  = (float*)smraw;
    float* sm_Zv = sm_m + 64;
    float* sm_ac = sm_Zv + 64;

    if (lane < 8) { sm_m[w * 8 + lane] = m; sm_Zv[w * 8 + lane] = Z; }
#pragma unroll
    for (int h = 0; h < H_; h++)
        *(float4*)&sm_ac[((size_t)w * 8 + h) * 128 + 4 * lane] = acc[h];
    __syncthreads();

    size_t base = ((size_t)b * NCHUNK + c) * H_;
#pragma unroll
    for (int it = 0; it < 4; it++) {
        int idx = tid + it * 256;
        int h = idx >> 7, d = idx & 127;
        float M = -CUDART_INF_F;
#pragma unroll
        for (int ww = 0; ww < 8; ww++) M = fmaxf(M, sm_m[ww * 8 + h]);
        float sacc = 0.f;
#pragma unroll
        for (int ww = 0; ww < 8; ww++) {
            float mw = sm_m[ww * 8 + h];
            float ee = (mw == -CUDART_INF_F) ? 0.f : __expf(mw - M);
            sacc = fmaf(ee, sm_ac[((size_t)ww * 8 + h) * 128 + d], sacc);
        }
        g_P[(base + h) * D_ + d] = sacc;
        if (d == 0) {
            float z = 0.f;
#pragma unroll
            for (int ww = 0; ww < 8; ww++) {
                float mw = sm_m[ww * 8 + h];
                float ee = (mw == -CUDART_INF_F) ? 0.f : __expf(mw - M);
                z = fmaf(ee, sm_Zv[ww * 8 + h], z);
            }
            g_S[base + h] = make_float2(M, z);
        }
    }
}

// ---------------------------------------------------------------------------
__global__ void dummy_kernel() {}

// ---------------------------------------------------------------------------
// Merge (R8 verbatim): combine 4 chunk-partials per (b,h), epilogue via
// g_Wv_eff. 256 threads, float4.
// ---------------------------------------------------------------------------
__global__ void __launch_bounds__(256)
merge_kernel(const float* __restrict__ Wo, float* __restrict__ out) {
    int b   = blockIdx.x;
    int a   = b % A_;
    int tid = threadIdx.x;

    __shared__ float4 pooled[H_ * 32];
    __shared__ float  ctx[H_ * DK_];
    __shared__ float  ec[NCHUNK][H_];
    __shared__ float  iZt[H_];

    if (tid < H_) {
        int h = tid;
        float mm[NCHUNK], zz[NCHUNK];
        float M = -CUDART_INF_F;
#pragma unroll
        for (int cc = 0; cc < NCHUNK; cc++) {
            float2 s = g_S[((size_t)b * NCHUNK + cc) * H_ + h];
            mm[cc] = s.x; zz[cc] = s.y;
            M = fmaxf(M, s.x);
        }
        float Zt = 0.f;
#pragma unroll
        for (int cc = 0; cc < NCHUNK; cc++) {
            float e = (mm[cc] == -CUDART_INF_F) ? 0.f : __expf(mm[cc] - M);
            ec[cc][h] = e;
            Zt = fmaf(e, zz[cc], Zt);
        }
        iZt[h] = 1.f / Zt;
    }
    __syncthreads();

    {
        int h = tid >> 5, d4 = tid & 31;
        const float4* P4 = (const float4*)g_P;
        float4 s = make_float4(0.f, 0.f, 0.f, 0.f);
#pragma unroll
        for (int cc = 0; cc < NCHUNK; cc++) {
            float4 v = P4[(((size_t)b * NCHUNK + cc) * H_ + h) * 32 + d4];
            float e = ec[cc][h];
            s.x = fmaf(e, v.x, s.x);
            s.y = fmaf(e, v.y, s.y);
            s.z = fmaf(e, v.z, s.z);
            s.w = fmaf(e, v.w, s.w);
        }
        float iz = iZt[h];
        s.x *= iz; s.y *= iz; s.z *= iz; s.w *= iz;
        pooled[h * 32 + d4] = s;
    }
    __syncthreads();

    if (tid < H_ * DK_) {
        int h = tid >> 4, k = tid & 15;
        const float* pl = (const float*)&pooled[h * 32];
        const float* wv = g_Wv_eff + h * (D_ + 1) * DK_ + k;
        float s = 0.f;
#pragma unroll 4
        for (int d = 0; d < D_; d++) s = fmaf(pl[d], wv[d * DK_], s);
        s = fmaf((float)a, wv[D_ * DK_], s);
        ctx[tid] = s;
    }
    __syncthreads();

    if (tid < D_) {
        int o = tid;
        float s = 0.f;
#pragma unroll 8
        for (int i = 0; i < H_ * DK_; i++)
            s = fmaf(ctx[i], Wo[i * D_ + o], s);
        out[(size_t)b * D_ + o] = s;
    }
}

// ---------------------------------------------------------------------------
extern "C" void kernel_launch(void* const* d_in, const int* in_sizes, int n_in,
                              void* d_out, int out_size) {
    const float* gc      = (const float*)d_in[0];
    const float* de      = (const float*)d_in[1];
    const float* tb      = (const float*)d_in[2];
    const float* load    = (const float*)d_in[3];
    const float* emb     = (const float*)d_in[4];
    const int*   lens    = (const int*)  d_in[5];
    const float* Wq_proj = (const float*)d_in[6];
    const float* Wk_proj = (const float*)d_in[7];
    const float* Wv_proj = (const float*)d_in[8];
    const float* Wq      = (const float*)d_in[9];
    const float* Wk      = (const float*)d_in[10];
    const float* Wv      = (const float*)d_in[11];
    const float* Wo      = (const float*)d_in[12];
    float* out = (float*)d_out;

    fold_kernel<<<24, 256>>>(Wq_proj, Wk_proj, Wv_proj, Wq, Wk, Wv);
    u_kernel<<<E_, 256>>>(gc, de, tb, load, Wq_proj);
    dummy_kernel<<<1, 32>>>();                 // pad so ncu idx3 = attn
    attn_kernel<<<NB_ * NCHUNK, 256>>>(emb, lens);
    merge_kernel<<<NB_, 256>>>(Wo, out);
}

// round 13
// speedup vs baseline: 2.7834x; 2.7834x over previous
#include <cuda_runtime.h>
#include <cstdint>
#include <math.h>
#include <math_constants.h>

typedef unsigned int u32;

#define E_  64
#define A_  8
#define L_  2048
#define D_  128
#define H_  8
#define DK_ 16

#define NB_     (E_ * A_)      // 512 (e,a) pairs
#define NCHUNK  4
#define CHUNK   (L_ / NCHUNK)  // 512 rows per chunk

#define NSTAGE  4
#define SROWS   24             // rows per stage (3 per warp)
#define STG_F4  (SROWS * 32)   // float4 per stage

// ---------------------------------------------------------------------------
// Device scratch (no cudaMalloc allowed)
// ---------------------------------------------------------------------------
__device__ float  g_U[NB_ * H_ * D_];            // folded query vectors (2 MB)
__device__ float  g_WkpT[D_ * D_];               // Wk_proj[0:128,:]^T  [j][d]
__device__ float  g_Wv_eff[H_ * (D_ + 1) * DK_]; // Wv_proj @ Wv[h]
__device__ float  g_P[NB_ * NCHUNK * H_ * D_];   // unnormalized partial acc
__device__ float2 g_S[NB_ * NCHUNK * H_];        // (m, Z) per partial

// ---------------------------------------------------------------------------
__device__ __forceinline__ void cp_async16(u32 dst, const void* src, int sz) {
    asm volatile("cp.async.cg.shared.global [%0], [%1], 16, %2;\n"
                 :: "r"(dst), "l"(src), "r"(sz) : "memory");
}
#define CP_COMMIT() asm volatile("cp.async.commit_group;\n" ::: "memory")
#define CP_WAIT3()  asm volatile("cp.async.wait_group 3;\n" ::: "memory")
#define CP_WAIT0()  asm volatile("cp.async.wait_group 0;\n" ::: "memory")

// ---------------------------------------------------------------------------
// prep_kernel: grid 24.
//   blocks [0,16):  32x32 tile transpose of Wk_proj[0:128,0:128] -> g_WkpT
//   blocks [16,24): h = bid-16 -> g_Wv_eff[h][d][k] = sum_j Wv_proj[d,j]*Wv[h][j,k]
// ---------------------------------------------------------------------------
__global__ void __launch_bounds__(256)
prep_kernel(const float* __restrict__ Wk_proj,
            const float* __restrict__ Wv_proj,
            const float* __restrict__ Wv) {
    int bid = blockIdx.x, tid = threadIdx.x;

    if (bid < 16) {
        __shared__ float sm[32 * 33];
        int tr = bid >> 2, tc = bid & 3;
        int tx = tid & 31, ty = tid >> 5;          // ty in 0..7
#pragma unroll
        for (int rr = 0; rr < 4; rr++) {
            int row = ty + rr * 8;
            sm[row * 33 + tx] = Wk_proj[(tr * 32 + row) * D_ + tc * 32 + tx];
        }
        __syncthreads();
#pragma unroll
        for (int rr = 0; rr < 4; rr++) {
            int row = ty + rr * 8;
            g_WkpT[(tc * 32 + row) * D_ + tr * 32 + tx] = sm[tx * 33 + row];
        }
        return;
    }

    // ---- Wv_eff (access pattern: <=2 lines per LDG, cheap) ----
    {
        int h = bid - 16;
        const float* wvh = Wv + h * (D_ * DK_);
        for (int idx = tid; idx < (D_ + 1) * DK_; idx += 256) {
            int d = idx >> 4, k = idx & 15;
            const float* wp = Wv_proj + d * D_;
            const float* wv = wvh + k;
            float s = 0.f;
#pragma unroll 4
            for (int j = 0; j < D_; j++) s = fmaf(wp[j], wv[j * DK_], s);
            g_Wv_eff[h * (D_ + 1) * DK_ + idx] = s;
        }
    }
}

// ---------------------------------------------------------------------------
// u_kernel: grid 64 (one CTA per e). Every stage coalesced or broadcast.
//   q[a][o]  = ctx@Wq_proj + per-agent rank-1 terms
//   qh[a][h][k] = sum_o q[a][o] * Wq[h][o,k]
//   t[a][h][j]  = sum_k Wk[h][j,k] * qh[a][h][k]   (Wk staged in swizzled smem)
//   u[a][h][d]  = 0.25 * sum_j WkpT[j][d] * t[a][h][j]
// ---------------------------------------------------------------------------
__global__ void __launch_bounds__(256)
u_kernel(const float* __restrict__ gc,  const float* __restrict__ de,
         const float* __restrict__ tb,  const float* __restrict__ load,
         const float* __restrict__ Wq_proj,
         const float* __restrict__ Wq,  const float* __restrict__ Wk) {
    int e   = blockIdx.x;
    int tid = threadIdx.x;

    __shared__ float q_s[A_ * D_];        // 4 KB
    __shared__ float qh_s[A_ * H_ * DK_]; // 4 KB  [a][h][k]
    __shared__ float t_s[A_ * H_ * D_];   // 32 KB [a][h][j]
    __shared__ float wk_s[D_ * DK_];      // 8 KB  swizzled [j][k]

    float* x_s = t_s;            // alias: [0..384)  (dead before t written)
    float* prt = t_s + 384;      // alias: [384..640)

    // ---- load context vector ----
    for (int i = tid; i < 384; i += 256) {
        float v;
        if (i < 128)      v = gc[e * D_ + i];
        else if (i < 256) v = de[e * D_ + (i - 128)];
        else              v = tb[e * D_ + (i - 256)];
        x_s[i] = v;
    }
    __syncthreads();

    // ---- q_ctx partials (coalesced: lane = o) ----
    {
        int o = tid & 127, half = tid >> 7;
        int i0 = half * 192, i1 = i0 + 192;
        float s = 0.f;
#pragma unroll 4
        for (int i = i0; i < i1; i++)
            s = fmaf(x_s[i], Wq_proj[i * D_ + o], s);
        prt[tid] = s;
    }
    __syncthreads();

    // ---- per-agent q ----
    if (tid < D_) {
        int o = tid;
        float qc = prt[o] + prt[o + 128];
        float wl = Wq_proj[384 * D_ + o];
        float wa = Wq_proj[385 * D_ + o];
#pragma unroll
        for (int a = 0; a < A_; a++) {
            float la = load[e * A_ + a];
            q_s[a * D_ + o] = fmaf(la, wl, fmaf((float)a, wa, qc));
        }
    }
    __syncthreads();

    // ---- qh[a][h][k] (Wq read: 16 consecutive floats -> <=2 lines/LDG) ----
#pragma unroll
    for (int it = 0; it < 4; it++) {
        int idx = it * 256 + tid;
        int a = idx >> 7, h = (idx >> 4) & 7, k = idx & 15;
        const float* wq = Wq + h * (D_ * DK_) + k;
        const float* qa = q_s + a * D_;
        float s = 0.f;
#pragma unroll 4
        for (int o = 0; o < D_; o++) s = fmaf(qa[o], wq[o * DK_], s);
        qh_s[idx] = s;
    }
    __syncthreads();

    // ---- t[a][h][j] via smem-staged swizzled Wk ----
    {
        int ah = tid >> 7;           // warp-uniform (warps 0-3: 0, 4-7: 1)
        int j  = tid & 127;
        int sw = (j >> 1) & 15;
        for (int h = 0; h < H_; h++) {
            for (int i = tid; i < D_ * DK_; i += 256) {
                int jj = i >> 4, kk = i & 15;
                wk_s[jj * 16 + (kk ^ ((jj >> 1) & 15))] = Wk[h * (D_ * DK_) + i];
            }
            __syncthreads();
#pragma unroll
            for (int ai = 0; ai < 4; ai++) {
                int a = ah * 4 + ai;
                const float* qh = qh_s + a * (H_ * DK_) + h * DK_;
                float s = 0.f;
#pragma unroll
                for (int k = 0; k < DK_; k++)
                    s = fmaf(wk_s[j * 16 + (k ^ sw)], qh[k], s);
                t_s[a * (H_ * D_) + h * D_ + j] = s;
            }
            __syncthreads();
        }
    }

    // ---- u[a][h][d] = 0.25 * sum_j WkpT[j][d] * t[a][h][j] (coalesced) ----
#pragma unroll
    for (int it = 0; it < 4; it++) {
        int idx = it * 256 + tid;
        int h = idx >> 7, d = idx & 127;
        float acc[A_];
#pragma unroll
        for (int a = 0; a < A_; a++) acc[a] = 0.f;
        const float* wT = g_WkpT + d;
        const float* tp = t_s + h * D_;
#pragma unroll 2
        for (int j = 0; j < D_; j++) {
            float wv = wT[j * D_];               // lanes d consecutive ✓
#pragma unroll
            for (int a = 0; a < A_; a++)
                acc[a] = fmaf(wv, tp[a * (H_ * D_) + j], acc[a]);
        }
#pragma unroll
        for (int a = 0; a < A_; a++)
            g_U[(((size_t)e * A_ + a) * H_ + h) * D_ + d] = 0.25f * acc[a];
    }
}

// ---------------------------------------------------------------------------
// fold8: per-lane partials p[0..7] (4 dims each) -> full 128-dot for head
// (lane & 7), replicated on all 4 lane-groups.
// ---------------------------------------------------------------------------
__device__ __forceinline__ float fold8(const float p[8], int lane) {
    const unsigned FULL = 0xffffffffu;
    int b0 = lane & 1, b1 = (lane >> 1) & 1, b2 = (lane >> 2) & 1;
    float q[4];
#pragma unroll
    for (int i = 0; i < 4; i++) {
        float t = b0 ? p[2 * i] : p[2 * i + 1];
        float r = __shfl_xor_sync(FULL, t, 1);
        q[i] = (b0 ? p[2 * i + 1] : p[2 * i]) + r;
    }
    float q2[2];
#pragma unroll
    for (int j = 0; j < 2; j++) {
        float t = b1 ? q[2 * j] : q[2 * j + 1];
        float r = __shfl_xor_sync(FULL, t, 2);
        q2[j] = (b1 ? q[2 * j + 1] : q[2 * j]) + r;
    }
    float t = b2 ? q2[0] : q2[1];
    float r = __shfl_xor_sync(FULL, t, 4);
    float s = (b2 ? q2[1] : q2[0]) + r;
    s += __shfl_xor_sync(FULL, s, 8);
    s += __shfl_xor_sync(FULL, s, 16);
    return s;
}

// ---------------------------------------------------------------------------
// attn kernel (R8/R12 verbatim, measured 116-123us)
// ---------------------------------------------------------------------------
__global__ void __launch_bounds__(256, 2)
attn_kernel(const float* __restrict__ emb, const int* __restrict__ lens) {
    const unsigned FULL = 0xffffffffu;
    int b    = blockIdx.x >> 2;
    int c    = blockIdx.x & 3;
    int tid  = threadIdx.x;
    int w    = tid >> 5;
    int lane = tid & 31;

    __shared__ __align__(16) char smraw[NSTAGE * STG_F4 * 16];   // 49152 B
    float4* stage = (float4*)smraw;

    int len  = lens[b];
    len = max(1, min(L_, len));
    int c0   = c * CHUNK;
    int cend = min(len, c0 + CHUNK);
    int nrows = max(0, cend - c0);
    int total = (nrows + SROWS - 1) / SROWS;

    const float4* src = (const float4*)(emb + (size_t)b * L_ * D_);

    float4 u[H_];
    {
        const float* ub = g_U + (size_t)b * H_ * D_ + 4 * lane;
#pragma unroll
        for (int h = 0; h < H_; h++) u[h] = *(const float4*)(ub + h * D_);
    }

    u32 smbase = (u32)__cvta_generic_to_shared(smraw);
    u32 my_off[3];
#pragma unroll
    for (int i = 0; i < 3; i++)
        my_off[i] = (u32)(((3 * w + i) * 32 + lane) * 16);

#pragma unroll
    for (int s = 0; s < NSTAGE; s++) {
        if (s < total) {
            int rbase = c0 + s * SROWS + 3 * w;
#pragma unroll
            for (int i = 0; i < 3; i++) {
                int gr = rbase + i;
                int ok = gr < cend;
                const void* sp = src + ((size_t)(ok ? gr : c0) * 32 + lane);
                cp_async16(smbase + (u32)(s * STG_F4 * 16) + my_off[i], sp, ok ? 16 : 0);
            }
        }
        CP_COMMIT();
    }

    float4 acc[H_];
#pragma unroll
    for (int h = 0; h < H_; h++) acc[h] = make_float4(0.f, 0.f, 0.f, 0.f);
    float m = -CUDART_INF_F, Z = 0.f;
    int g = lane >> 3;

    for (int s = 0; s < total; s++) {
        CP_WAIT3();
        int buf = s & 3;
        const float4* st = stage + buf * STG_F4;
        int lr = 3 * w;
        float4 e0 = st[(lr + 0) * 32 + lane];
        float4 e1 = st[(lr + 1) * 32 + lane];
        float4 e2 = st[(lr + 2) * 32 + lane];

        float s0, s1, s2;
        {
            float pa[8];
#pragma unroll
            for (int h = 0; h < H_; h++) {
                float t = e0.x * u[h].x;
                t = fmaf(e0.y, u[h].y, t);
                t = fmaf(e0.z, u[h].z, t);
                pa[h] = fmaf(e0.w, u[h].w, t);
            }
            s0 = fold8(pa, lane);
#pragma unroll
            for (int h = 0; h < H_; h++) {
                float t = e1.x * u[h].x;
                t = fmaf(e1.y, u[h].y, t);
                t = fmaf(e1.z, u[h].z, t);
                pa[h] = fmaf(e1.w, u[h].w, t);
            }
            s1 = fold8(pa, lane);
#pragma unroll
            for (int h = 0; h < H_; h++) {
                float t = e2.x * u[h].x;
                t = fmaf(e2.y, u[h].y, t);
                t = fmaf(e2.z, u[h].z, t);
                pa[h] = fmaf(e2.w, u[h].w, t);
            }
            s2 = fold8(pa, lane);
        }

        {
            int sn = s + NSTAGE;
            if (sn < total) {
                int rbase = c0 + sn * SROWS + 3 * w;
#pragma unroll
                for (int i = 0; i < 3; i++) {
                    int gr = rbase + i;
                    int ok = gr < cend;
                    const void* sp = src + ((size_t)(ok ? gr : c0) * 32 + lane);
                    cp_async16(smbase + (u32)(buf * STG_F4 * 16) + my_off[i], sp, ok ? 16 : 0);
                }
            }
            CP_COMMIT();
        }

        int rbase = c0 + s * SROWS + 3 * w;
        if (rbase + 0 >= cend) s0 = -CUDART_INF_F;
        if (rbase + 1 >= cend) s1 = -CUDART_INF_F;
        if (rbase + 2 >= cend) s2 = -CUDART_INF_F;

        float bm = fmaxf(fmaxf(s0, s1), s2);
        if (__any_sync(FULL, bm > m)) {
            float mn = fmaxf(m, bm);
            float cs = __expf(m - mn);
            m = mn;
            Z *= cs;
#pragma unroll
            for (int h = 0; h < H_; h++) {
                float ch = __shfl_sync(FULL, cs, h);
                acc[h].x *= ch; acc[h].y *= ch; acc[h].z *= ch; acc[h].w *= ch;
            }
        }

        float sg = (g == 0) ? s0 : ((g == 1) ? s1 : s2);
        float pg = (g < 3 && sg > -CUDART_INF_F) ? __expf(sg - m) : 0.f;

        float zs = pg + __shfl_xor_sync(FULL, pg, 8);
        zs += __shfl_xor_sync(FULL, zs, 16);
        Z += zs;

#pragma unroll
        for (int h = 0; h < H_; h++) {
            float p0 = __shfl_sync(FULL, pg, 0 * 8 + h);
            acc[h].x = fmaf(p0, e0.x, acc[h].x);
            acc[h].y = fmaf(p0, e0.y, acc[h].y);
            acc[h].z = fmaf(p0, e0.z, acc[h].z);
            acc[h].w = fmaf(p0, e0.w, acc[h].w);
        }
#pragma unroll
        for (int h = 0; h < H_; h++) {
            float p1 = __shfl_sync(FULL, pg, 1 * 8 + h);
            acc[h].x = fmaf(p1, e1.x, acc[h].x);
            acc[h].y = fmaf(p1, e1.y, acc[h].y);
            acc[h].z = fmaf(p1, e1.z, acc[h].z);
            acc[h].w = fmaf(p1, e1.w, acc[h].w);
        }
#pragma unroll
        for (int h = 0; h < H_; h++) {
            float p2 = __shfl_sync(FULL, pg, 2 * 8 + h);
            acc[h].x = fmaf(p2, e2.x, acc[h].x);
            acc[h].y = fmaf(p2, e2.y, acc[h].y);
            acc[h].z = fmaf(p2, e2.z, acc[h].z);
            acc[h].w = fmaf(p2, e2.w, acc[h].w);
        }
    }

    CP_WAIT0();
    __syncthreads();

    float* sm_m  = (float*)smraw;
    float* sm_Zv = sm_m + 64;
    float* sm_ac = sm_Zv + 64;

    if (lane < 8) { sm_m[w * 8 + lane] = m; sm_Zv[w * 8 + lane] = Z; }
#pragma unroll
    for (int h = 0; h < H_; h++)
        *(float4*)&sm_ac[((size_t)w * 8 + h) * 128 + 4 * lane] = acc[h];
    __syncthreads();

    size_t base = ((size_t)b * NCHUNK + c) * H_;
#pragma unroll
    for (int it = 0; it < 4; it++) {
        int idx = tid + it * 256;
        int h = idx >> 7, d = idx & 127;
        float M = -CUDART_INF_F;
#pragma unroll
        for (int ww = 0; ww < 8; ww++) M = fmaxf(M, sm_m[ww * 8 + h]);
        float sacc = 0.f;
#pragma unroll
        for (int ww = 0; ww < 8; ww++) {
            float mw = sm_m[ww * 8 + h];
            float ee = (mw == -CUDART_INF_F) ? 0.f : __expf(mw - M);
            sacc = fmaf(ee, sm_ac[((size_t)ww * 8 + h) * 128 + d], sacc);
        }
        g_P[(base + h) * D_ + d] = sacc;
        if (d == 0) {
            float z = 0.f;
#pragma unroll
            for (int ww = 0; ww < 8; ww++) {
                float mw = sm_m[ww * 8 + h];
                float ee = (mw == -CUDART_INF_F) ? 0.f : __expf(mw - M);
                z = fmaf(ee, sm_Zv[ww * 8 + h], z);
            }
            g_S[base + h] = make_float2(M, z);
        }
    }
}

// ---------------------------------------------------------------------------
__global__ void dummy_kernel() {}

// ---------------------------------------------------------------------------
// Merge (R12 verbatim, measured ~30us)
// ---------------------------------------------------------------------------
__global__ void __launch_bounds__(256)
merge_kernel(const float* __restrict__ Wo, float* __restrict__ out) {
    int b   = blockIdx.x;
    int a   = b % A_;
    int tid = threadIdx.x;

    __shared__ float4 pooled[H_ * 32];
    __shared__ float  ctx[H_ * DK_];
    __shared__ float  ec[NCHUNK][H_];
    __shared__ float  iZt[H_];

    if (tid < H_) {
        int h = tid;
        float mm[NCHUNK], zz[NCHUNK];
        float M = -CUDART_INF_F;
#pragma unroll
        for (int cc = 0; cc < NCHUNK; cc++) {
            float2 s = g_S[((size_t)b * NCHUNK + cc) * H_ + h];
            mm[cc] = s.x; zz[cc] = s.y;
            M = fmaxf(M, s.x);
        }
        float Zt = 0.f;
#pragma unroll
        for (int cc = 0; cc < NCHUNK; cc++) {
            float e = (mm[cc] == -CUDART_INF_F) ? 0.f : __expf(mm[cc] - M);
            ec[cc][h] = e;
            Zt = fmaf(e, zz[cc], Zt);
        }
        iZt[h] = 1.f / Zt;
    }
    __syncthreads();

    {
        int h = tid >> 5, d4 = tid & 31;
        const float4* P4 = (const float4*)g_P;
        float4 s = make_float4(0.f, 0.f, 0.f, 0.f);
#pragma unroll
        for (int cc = 0; cc < NCHUNK; cc++) {
            float4 v = P4[(((size_t)b * NCHUNK + cc) * H_ + h) * 32 + d4];
            float e = ec[cc][h];
            s.x = fmaf(e, v.x, s.x);
            s.y = fmaf(e, v.y, s.y);
            s.z = fmaf(e, v.z, s.z);
            s.w = fmaf(e, v.w, s.w);
        }
        float iz = iZt[h];
        s.x *= iz; s.y *= iz; s.z *= iz; s.w *= iz;
        pooled[h * 32 + d4] = s;
    }
    __syncthreads();

    if (tid < H_ * DK_) {
        int h = tid >> 4, k = tid & 15;
        const float* pl = (const float*)&pooled[h * 32];
        const float* wv = g_Wv_eff + h * (D_ + 1) * DK_ + k;
        float s = 0.f;
#pragma unroll 4
        for (int d = 0; d < D_; d++) s = fmaf(pl[d], wv[d * DK_], s);
        s = fmaf((float)a, wv[D_ * DK_], s);
        ctx[tid] = s;
    }
    __syncthreads();

    if (tid < D_) {
        int o = tid;
        float s = 0.f;
#pragma unroll 8
        for (int i = 0; i < H_ * DK_; i++)
            s = fmaf(ctx[i], Wo[i * D_ + o], s);
        out[(size_t)b * D_ + o] = s;
    }
}

// ---------------------------------------------------------------------------
extern "C" void kernel_launch(void* const* d_in, const int* in_sizes, int n_in,
                              void* d_out, int out_size) {
    const float* gc      = (const float*)d_in[0];
    const float* de      = (const float*)d_in[1];
    const float* tb      = (const float*)d_in[2];
    const float* load    = (const float*)d_in[3];
    const float* emb     = (const float*)d_in[4];
    const int*   lens    = (const int*)  d_in[5];
    const float* Wq_proj = (const float*)d_in[6];
    const float* Wk_proj = (const float*)d_in[7];
    const float* Wv_proj = (const float*)d_in[8];
    const float* Wq      = (const float*)d_in[9];
    const float* Wk      = (const float*)d_in[10];
    const float* Wv      = (const float*)d_in[11];
    const float* Wo      = (const float*)d_in[12];
    float* out = (float*)d_out;

    prep_kernel<<<24, 256>>>(Wk_proj, Wv_proj, Wv);
    u_kernel<<<E_, 256>>>(gc, de, tb, load, Wq_proj, Wq, Wk);
    dummy_kernel<<<1, 32>>>();                 // pad so ncu idx3 = attn
    attn_kernel<<<NB_ * NCHUNK, 256>>>(emb, lens);
    merge_kernel<<<NB_, 256>>>(Wo, out);
}